// round 16
// baseline (speedup 1.0000x reference)
#include <cuda_runtime.h>

// Group ZCA whitening: x (64, 256, 56, 56) fp32, 64 groups of 4 channels.
// R16: R15 base (best: 104.5us) with apply's grid restored to R10's ordering:
// (NG, NB) with g FASTEST (reversed) -> consecutively-scheduled apply blocks
// read contiguous addresses (R10 measured 61.6us/72.8% DRAM vs 64.4/68.6 for
// the b-fastest variant). Stats unchanged: (NB, NG) b-fastest so groups
// complete early and NS solves trickle; PDL overlap unchanged.

#define NB   64      // batches
#define NG   64      // groups
#define NCH  256     // channels
#define SP   3136    // 56*56
#define SP4  784     // SP / 4
#define EPSF 1e-3f

__device__ float g_part[NG * NB * 14];   // [group][batch][4 sums + 10 moments]
__device__ float g_W[NG * 16];
__device__ float g_bias[NG * 4];
__device__ unsigned int g_cnt[NG];       // per-group arrival counters (self-resetting)

// ---------------------------------------------------------------------------
// Warp-parallel Newton-Schulz inverse-sqrt solve for group g. 16 threads own
// one 4x4 element each; matmuls via shuffles. W = (C_shrunk + eps I)^{-1/2}
// == U diag(1/sqrt(s+eps)) U^T of the reference.
// ---------------------------------------------------------------------------
__device__ void solve_group(int g) {
    const int t = threadIdx.x;

    float vals[14];
    if (t < NB) {
        #pragma unroll
        for (int k = 0; k < 14; k++)
            vals[k] = g_part[((size_t)g * NB + t) * 14 + k];
    } else {
        #pragma unroll
        for (int k = 0; k < 14; k++) vals[k] = 0.f;
    }
    const int lane = t & 31;
    const int warp = t >> 5;
    #pragma unroll
    for (int k = 0; k < 14; k++) {
        #pragma unroll
        for (int o = 16; o > 0; o >>= 1)
            vals[k] += __shfl_down_sync(0xffffffffu, vals[k], o);
    }
    __shared__ float sv[2][14];
    if (lane == 0 && warp < 2) {
        #pragma unroll
        for (int k = 0; k < 14; k++) sv[warp][k] = vals[k];
    }
    __syncthreads();

    if (t < 16) {
        const unsigned int MASK = 0xFFFFu;
        const int i = t >> 2;
        const int j = t & 3;

        float S[4], Q[10];
        #pragma unroll
        for (int k = 0; k < 4; k++) S[k] = sv[0][k] + sv[1][k];
        #pragma unroll
        for (int k = 0; k < 10; k++) Q[k] = sv[0][4 + k] + sv[1][4 + k];

        const float n = (float)NB * (float)SP;
        float m[4];
        #pragma unroll
        for (int k = 0; k < 4; k++) m[k] = S[k] / n;

        const int qi[4][4] = {{0,1,2,3},{1,4,5,6},{2,5,7,8},{3,6,8,9}};
        float cov = Q[qi[i][j]] - n * m[i] * m[j];
        float B = (1.0f - EPSF) * cov + ((i == j) ? 2.0f * EPSF : 0.0f);

        float b00 = __shfl_sync(MASK, B, 0);
        float b11 = __shfl_sync(MASK, B, 5);
        float b22 = __shfl_sync(MASK, B, 10);
        float b33 = __shfl_sync(MASK, B, 15);
        float c = b00 + b11 + b22 + b33;

        float y = B / c;                      // Y0 = B / tr(B)
        float z = (i == j) ? 1.0f : 0.0f;     // Z0 = I

        #pragma unroll
        for (int iter = 0; iter < 12; iter++) {
            float tsum = 0.f;
            #pragma unroll
            for (int k = 0; k < 4; k++)
                tsum = fmaf(__shfl_sync(MASK, z, i * 4 + k),
                            __shfl_sync(MASK, y, k * 4 + j), tsum);
            float mm = ((i == j) ? 1.5f : 0.0f) - 0.5f * tsum;
            float ynew = 0.f, znew = 0.f;
            #pragma unroll
            for (int k = 0; k < 4; k++) {
                ynew = fmaf(__shfl_sync(MASK, y, i * 4 + k),
                            __shfl_sync(MASK, mm, k * 4 + j), ynew);
                znew = fmaf(__shfl_sync(MASK, mm, i * 4 + k),
                            __shfl_sync(MASK, z, k * 4 + j), znew);
            }
            y = ynew;
            z = znew;
        }

        float W = z * rsqrtf(c);
        g_W[g * 16 + t] = W;

        float bi = W * m[j];
        bi += __shfl_xor_sync(MASK, bi, 1);
        bi += __shfl_xor_sync(MASK, bi, 2);
        if (j == 0) g_bias[g * 4 + i] = bi;
    }
}

// ---------------------------------------------------------------------------
// Pass 1: stats + inline last-block solve. grid (NB, NG), b fastest (groups
// complete early & staggered; NS solves trickle during streaming).
// ---------------------------------------------------------------------------
__global__ __launch_bounds__(256, 6) void stats_kernel(const float* __restrict__ x) {
    const int b = blockIdx.x;
    const int g = blockIdx.y;
    const int tid = threadIdx.x;
    const size_t base = ((size_t)b * NCH + (size_t)g * 4) * SP;
    const float4* __restrict__ c0 = (const float4*)(x + base);
    const float4* __restrict__ c1 = c0 + SP4;
    const float4* __restrict__ c2 = c0 + 2 * SP4;
    const float4* __restrict__ c3 = c0 + 3 * SP4;

    float s0 = 0.f, s1 = 0.f, s2 = 0.f, s3 = 0.f;
    float q00 = 0.f, q01 = 0.f, q02 = 0.f, q03 = 0.f;
    float q11 = 0.f, q12 = 0.f, q13 = 0.f;
    float q22 = 0.f, q23 = 0.f, q33 = 0.f;

    for (int i = tid; i < SP4; i += 256) {
        float4 a = c0[i];
        float4 e = c1[i];
        float4 f = c2[i];
        float4 h = c3[i];
        s0 += a.x + a.y + a.z + a.w;
        s1 += e.x + e.y + e.z + e.w;
        s2 += f.x + f.y + f.z + f.w;
        s3 += h.x + h.y + h.z + h.w;
        q00 += a.x*a.x + a.y*a.y + a.z*a.z + a.w*a.w;
        q01 += a.x*e.x + a.y*e.y + a.z*e.z + a.w*e.w;
        q02 += a.x*f.x + a.y*f.y + a.z*f.z + a.w*f.w;
        q03 += a.x*h.x + a.y*h.y + a.z*h.z + a.w*h.w;
        q11 += e.x*e.x + e.y*e.y + e.z*e.z + e.w*e.w;
        q12 += e.x*f.x + e.y*f.y + e.z*f.z + e.w*f.w;
        q13 += e.x*h.x + e.y*h.y + e.z*h.z + e.w*h.w;
        q22 += f.x*f.x + f.y*f.y + f.z*f.z + f.w*f.w;
        q23 += f.x*h.x + f.y*h.y + f.z*h.z + f.w*h.w;
        q33 += h.x*h.x + h.y*h.y + h.z*h.z + h.w*h.w;
    }

    float vals[14] = {s0, s1, s2, s3, q00, q01, q02, q03, q11, q12, q13, q22, q23, q33};

    const int lane = tid & 31;
    const int warp = tid >> 5;
    #pragma unroll
    for (int k = 0; k < 14; k++) {
        #pragma unroll
        for (int o = 16; o > 0; o >>= 1)
            vals[k] += __shfl_down_sync(0xffffffffu, vals[k], o);
    }

    __shared__ float sm[8][14];
    if (lane == 0) {
        #pragma unroll
        for (int k = 0; k < 14; k++) sm[warp][k] = vals[k];
    }
    __syncthreads();
    if (tid < 14) {
        float t = 0.f;
        #pragma unroll
        for (int w = 0; w < 8; w++) t += sm[w][tid];
        g_part[((size_t)g * NB + b) * 14 + tid] = t;
    }

    __shared__ unsigned int is_last;
    __syncthreads();
    if (tid == 0) {
        __threadfence();                       // publish g_part writes
        unsigned int old = atomicAdd(&g_cnt[g], 1u);
        is_last = (old == NB - 1u) ? 1u : 0u;
        if (is_last) atomicExch(&g_cnt[g], 0u);  // reset for graph replay
    }
    __syncthreads();

    // PDL: streaming contribution done -> let the apply grid start launching.
    asm volatile("griddepcontrol.launch_dependents;" ::: "memory");

    if (is_last) {
        solve_group(g);
    }
}

// ---------------------------------------------------------------------------
// Pass 2: apply. grid (NG, NB), g FASTEST, fully reversed -> consecutive
// blocks read contiguous addresses AND consume stats' L2 residue first.
// PDL secondary: wait for stats grid completion before consuming W/bias.
// ---------------------------------------------------------------------------
__global__ __launch_bounds__(256) void apply_kernel(const float* __restrict__ x,
                                                    float* __restrict__ out) {
    const int g = NG - 1 - blockIdx.x;   // reverse g (fast dim)
    const int b = NB - 1 - blockIdx.y;   // reverse b (slow dim)
    const int tid = threadIdx.x;

    asm volatile("griddepcontrol.wait;" ::: "memory");

    __shared__ float Ws[20];
    if (tid < 16) Ws[tid] = g_W[g * 16 + tid];
    if (tid < 4)  Ws[16 + tid] = g_bias[g * 4 + tid];
    __syncthreads();

    const float w00 = Ws[0],  w01 = Ws[1],  w02 = Ws[2],  w03 = Ws[3];
    const float w10 = Ws[4],  w11 = Ws[5],  w12 = Ws[6],  w13 = Ws[7];
    const float w20 = Ws[8],  w21 = Ws[9],  w22 = Ws[10], w23 = Ws[11];
    const float w30 = Ws[12], w31 = Ws[13], w32 = Ws[14], w33 = Ws[15];
    const float b0 = Ws[16], b1 = Ws[17], b2 = Ws[18], b3 = Ws[19];

    const size_t base = ((size_t)b * NCH + (size_t)g * 4) * SP;
    const float4* __restrict__ c0 = (const float4*)(x + base);
    const float4* __restrict__ c1 = c0 + SP4;
    const float4* __restrict__ c2 = c0 + 2 * SP4;
    const float4* __restrict__ c3 = c0 + 3 * SP4;
    float4* __restrict__ o0 = (float4*)(out + base);
    float4* __restrict__ o1 = o0 + SP4;
    float4* __restrict__ o2 = o0 + 2 * SP4;
    float4* __restrict__ o3 = o0 + 3 * SP4;

    for (int i = tid; i < SP4; i += 256) {
        float4 a = __ldcs(c0 + i);
        float4 e = __ldcs(c1 + i);
        float4 f = __ldcs(c2 + i);
        float4 h = __ldcs(c3 + i);

        float4 r0, r1, r2, r3;
        r0.x = fmaf(w00, a.x, fmaf(w01, e.x, fmaf(w02, f.x, fmaf(w03, h.x, -b0))));
        r0.y = fmaf(w00, a.y, fmaf(w01, e.y, fmaf(w02, f.y, fmaf(w03, h.y, -b0))));
        r0.z = fmaf(w00, a.z, fmaf(w01, e.z, fmaf(w02, f.z, fmaf(w03, h.z, -b0))));
        r0.w = fmaf(w00, a.w, fmaf(w01, e.w, fmaf(w02, f.w, fmaf(w03, h.w, -b0))));
        r1.x = fmaf(w10, a.x, fmaf(w11, e.x, fmaf(w12, f.x, fmaf(w13, h.x, -b1))));
        r1.y = fmaf(w10, a.y, fmaf(w11, e.y, fmaf(w12, f.y, fmaf(w13, h.y, -b1))));
        r1.z = fmaf(w10, a.z, fmaf(w11, e.z, fmaf(w12, f.z, fmaf(w13, h.z, -b1))));
        r1.w = fmaf(w10, a.w, fmaf(w11, e.w, fmaf(w12, f.w, fmaf(w13, h.w, -b1))));
        r2.x = fmaf(w20, a.x, fmaf(w21, e.x, fmaf(w22, f.x, fmaf(w23, h.x, -b2))));
        r2.y = fmaf(w20, a.y, fmaf(w21, e.y, fmaf(w22, f.y, fmaf(w23, h.y, -b2))));
        r2.z = fmaf(w20, a.z, fmaf(w21, e.z, fmaf(w22, f.z, fmaf(w23, h.z, -b2))));
        r2.w = fmaf(w20, a.w, fmaf(w21, e.w, fmaf(w22, f.w, fmaf(w23, h.w, -b2))));
        r3.x = fmaf(w30, a.x, fmaf(w31, e.x, fmaf(w32, f.x, fmaf(w33, h.x, -b3))));
        r3.y = fmaf(w30, a.y, fmaf(w31, e.y, fmaf(w32, f.y, fmaf(w33, h.y, -b3))));
        r3.z = fmaf(w30, a.z, fmaf(w31, e.z, fmaf(w32, f.z, fmaf(w33, h.z, -b3))));
        r3.w = fmaf(w30, a.w, fmaf(w31, e.w, fmaf(w32, f.w, fmaf(w33, h.w, -b3))));

        __stcs(o0 + i, r0);
        __stcs(o1 + i, r1);
        __stcs(o2 + i, r2);
        __stcs(o3 + i, r3);
    }
}

// ---------------------------------------------------------------------------
extern "C" void kernel_launch(void* const* d_in, const int* in_sizes, int n_in,
                              void* d_out, int out_size) {
    const float* x = (const float*)d_in[0];
    float* out = (float*)d_out;

    stats_kernel<<<dim3(NB, NG), 256>>>(x);

    cudaLaunchConfig_t cfg = {};
    cfg.gridDim = dim3(NG, NB);
    cfg.blockDim = dim3(256);
    cfg.dynamicSmemBytes = 0;
    cfg.stream = 0;
    cudaLaunchAttribute attrs[1];
    attrs[0].id = cudaLaunchAttributeProgrammaticStreamSerialization;
    attrs[0].val.programmaticStreamSerializationAllowed = 1;
    cfg.attrs = attrs;
    cfg.numAttrs = 1;
    cudaLaunchKernelEx(&cfg, apply_kernel, x, out);
}

// round 17
// speedup vs baseline: 1.0046x; 1.0046x over previous
#include <cuda_runtime.h>

// Group ZCA whitening: x (64, 256, 56, 56) fp32, 64 groups of 4 channels.
// R17: R16 base. Model: both passes saturate LTS (~5.8 TB/s), total LTS
// traffic 615MB -> ~104us structural floor. Last recoverable slack is the
// per-block PDL-wait bubble in apply: hoist the FIRST iteration's x loads
// (x is independent of the stats grid) above griddepcontrol.wait, so each
// apply block's first memory latency overlaps the wait / stats tail.
// Zero added instructions (pure reorder, unlike R14's prefetch loop).

#define NB   64      // batches
#define NG   64      // groups
#define NCH  256     // channels
#define SP   3136    // 56*56
#define SP4  784     // SP / 4
#define EPSF 1e-3f

__device__ float g_part[NG * NB * 14];   // [group][batch][4 sums + 10 moments]
__device__ float g_W[NG * 16];
__device__ float g_bias[NG * 4];
__device__ unsigned int g_cnt[NG];       // per-group arrival counters (self-resetting)

// ---------------------------------------------------------------------------
// Warp-parallel Newton-Schulz inverse-sqrt solve for group g. 16 threads own
// one 4x4 element each; matmuls via shuffles. W = (C_shrunk + eps I)^{-1/2}
// == U diag(1/sqrt(s+eps)) U^T of the reference.
// ---------------------------------------------------------------------------
__device__ void solve_group(int g) {
    const int t = threadIdx.x;

    float vals[14];
    if (t < NB) {
        #pragma unroll
        for (int k = 0; k < 14; k++)
            vals[k] = g_part[((size_t)g * NB + t) * 14 + k];
    } else {
        #pragma unroll
        for (int k = 0; k < 14; k++) vals[k] = 0.f;
    }
    const int lane = t & 31;
    const int warp = t >> 5;
    #pragma unroll
    for (int k = 0; k < 14; k++) {
        #pragma unroll
        for (int o = 16; o > 0; o >>= 1)
            vals[k] += __shfl_down_sync(0xffffffffu, vals[k], o);
    }
    __shared__ float sv[2][14];
    if (lane == 0 && warp < 2) {
        #pragma unroll
        for (int k = 0; k < 14; k++) sv[warp][k] = vals[k];
    }
    __syncthreads();

    if (t < 16) {
        const unsigned int MASK = 0xFFFFu;
        const int i = t >> 2;
        const int j = t & 3;

        float S[4], Q[10];
        #pragma unroll
        for (int k = 0; k < 4; k++) S[k] = sv[0][k] + sv[1][k];
        #pragma unroll
        for (int k = 0; k < 10; k++) Q[k] = sv[0][4 + k] + sv[1][4 + k];

        const float n = (float)NB * (float)SP;
        float m[4];
        #pragma unroll
        for (int k = 0; k < 4; k++) m[k] = S[k] / n;

        const int qi[4][4] = {{0,1,2,3},{1,4,5,6},{2,5,7,8},{3,6,8,9}};
        float cov = Q[qi[i][j]] - n * m[i] * m[j];
        float B = (1.0f - EPSF) * cov + ((i == j) ? 2.0f * EPSF : 0.0f);

        float b00 = __shfl_sync(MASK, B, 0);
        float b11 = __shfl_sync(MASK, B, 5);
        float b22 = __shfl_sync(MASK, B, 10);
        float b33 = __shfl_sync(MASK, B, 15);
        float c = b00 + b11 + b22 + b33;

        float y = B / c;                      // Y0 = B / tr(B)
        float z = (i == j) ? 1.0f : 0.0f;     // Z0 = I

        #pragma unroll
        for (int iter = 0; iter < 12; iter++) {
            float tsum = 0.f;
            #pragma unroll
            for (int k = 0; k < 4; k++)
                tsum = fmaf(__shfl_sync(MASK, z, i * 4 + k),
                            __shfl_sync(MASK, y, k * 4 + j), tsum);
            float mm = ((i == j) ? 1.5f : 0.0f) - 0.5f * tsum;
            float ynew = 0.f, znew = 0.f;
            #pragma unroll
            for (int k = 0; k < 4; k++) {
                ynew = fmaf(__shfl_sync(MASK, y, i * 4 + k),
                            __shfl_sync(MASK, mm, k * 4 + j), ynew);
                znew = fmaf(__shfl_sync(MASK, mm, i * 4 + k),
                            __shfl_sync(MASK, z, k * 4 + j), znew);
            }
            y = ynew;
            z = znew;
        }

        float W = z * rsqrtf(c);
        g_W[g * 16 + t] = W;

        float bi = W * m[j];
        bi += __shfl_xor_sync(MASK, bi, 1);
        bi += __shfl_xor_sync(MASK, bi, 2);
        if (j == 0) g_bias[g * 4 + i] = bi;
    }
}

// ---------------------------------------------------------------------------
// Pass 1: stats + inline last-block solve. grid (NB, NG), b fastest (groups
// complete early & staggered; NS solves trickle during streaming).
// ---------------------------------------------------------------------------
__global__ __launch_bounds__(256, 6) void stats_kernel(const float* __restrict__ x) {
    const int b = blockIdx.x;
    const int g = blockIdx.y;
    const int tid = threadIdx.x;
    const size_t base = ((size_t)b * NCH + (size_t)g * 4) * SP;
    const float4* __restrict__ c0 = (const float4*)(x + base);
    const float4* __restrict__ c1 = c0 + SP4;
    const float4* __restrict__ c2 = c0 + 2 * SP4;
    const float4* __restrict__ c3 = c0 + 3 * SP4;

    float s0 = 0.f, s1 = 0.f, s2 = 0.f, s3 = 0.f;
    float q00 = 0.f, q01 = 0.f, q02 = 0.f, q03 = 0.f;
    float q11 = 0.f, q12 = 0.f, q13 = 0.f;
    float q22 = 0.f, q23 = 0.f, q33 = 0.f;

    for (int i = tid; i < SP4; i += 256) {
        float4 a = c0[i];
        float4 e = c1[i];
        float4 f = c2[i];
        float4 h = c3[i];
        s0 += a.x + a.y + a.z + a.w;
        s1 += e.x + e.y + e.z + e.w;
        s2 += f.x + f.y + f.z + f.w;
        s3 += h.x + h.y + h.z + h.w;
        q00 += a.x*a.x + a.y*a.y + a.z*a.z + a.w*a.w;
        q01 += a.x*e.x + a.y*e.y + a.z*e.z + a.w*e.w;
        q02 += a.x*f.x + a.y*f.y + a.z*f.z + a.w*f.w;
        q03 += a.x*h.x + a.y*h.y + a.z*h.z + a.w*h.w;
        q11 += e.x*e.x + e.y*e.y + e.z*e.z + e.w*e.w;
        q12 += e.x*f.x + e.y*f.y + e.z*f.z + e.w*f.w;
        q13 += e.x*h.x + e.y*h.y + e.z*h.z + e.w*h.w;
        q22 += f.x*f.x + f.y*f.y + f.z*f.z + f.w*f.w;
        q23 += f.x*h.x + f.y*h.y + f.z*h.z + f.w*h.w;
        q33 += h.x*h.x + h.y*h.y + h.z*h.z + h.w*h.w;
    }

    float vals[14] = {s0, s1, s2, s3, q00, q01, q02, q03, q11, q12, q13, q22, q23, q33};

    const int lane = tid & 31;
    const int warp = tid >> 5;
    #pragma unroll
    for (int k = 0; k < 14; k++) {
        #pragma unroll
        for (int o = 16; o > 0; o >>= 1)
            vals[k] += __shfl_down_sync(0xffffffffu, vals[k], o);
    }

    __shared__ float sm[8][14];
    if (lane == 0) {
        #pragma unroll
        for (int k = 0; k < 14; k++) sm[warp][k] = vals[k];
    }
    __syncthreads();
    if (tid < 14) {
        float t = 0.f;
        #pragma unroll
        for (int w = 0; w < 8; w++) t += sm[w][tid];
        g_part[((size_t)g * NB + b) * 14 + tid] = t;
    }

    __shared__ unsigned int is_last;
    __syncthreads();
    if (tid == 0) {
        __threadfence();                       // publish g_part writes
        unsigned int old = atomicAdd(&g_cnt[g], 1u);
        is_last = (old == NB - 1u) ? 1u : 0u;
        if (is_last) atomicExch(&g_cnt[g], 0u);  // reset for graph replay
    }
    __syncthreads();

    // PDL: streaming contribution done -> let the apply grid start launching.
    asm volatile("griddepcontrol.launch_dependents;" ::: "memory");

    if (is_last) {
        solve_group(g);
    }
}

// ---------------------------------------------------------------------------
// Pass 2: apply. grid (NG, NB), g FASTEST, fully reversed -> consecutive
// blocks read contiguous addresses AND consume stats' L2 residue first.
// First iteration's x loads are issued BEFORE griddepcontrol.wait (x is
// independent of the primary grid), hiding the wait bubble.
// ---------------------------------------------------------------------------
__global__ __launch_bounds__(256) void apply_kernel(const float* __restrict__ x,
                                                    float* __restrict__ out) {
    const int g = NG - 1 - blockIdx.x;   // reverse g (fast dim)
    const int b = NB - 1 - blockIdx.y;   // reverse b (slow dim)
    const int tid = threadIdx.x;

    const size_t base = ((size_t)b * NCH + (size_t)g * 4) * SP;
    const float4* __restrict__ c0 = (const float4*)(x + base);
    const float4* __restrict__ c1 = c0 + SP4;
    const float4* __restrict__ c2 = c0 + 2 * SP4;
    const float4* __restrict__ c3 = c0 + 3 * SP4;

    // Hoisted first-iteration loads (tid < 784 always): issue before the PDL
    // wait so their latency overlaps the stats tail / wait bubble.
    float4 a0 = __ldcs(c0 + tid);
    float4 e0 = __ldcs(c1 + tid);
    float4 f0 = __ldcs(c2 + tid);
    float4 h0 = __ldcs(c3 + tid);

    // Wait for the stats grid to fully complete (makes g_W/g_bias visible).
    asm volatile("griddepcontrol.wait;" ::: "memory");

    __shared__ float Ws[20];
    if (tid < 16) Ws[tid] = g_W[g * 16 + tid];
    if (tid < 4)  Ws[16 + tid] = g_bias[g * 4 + tid];
    __syncthreads();

    const float w00 = Ws[0],  w01 = Ws[1],  w02 = Ws[2],  w03 = Ws[3];
    const float w10 = Ws[4],  w11 = Ws[5],  w12 = Ws[6],  w13 = Ws[7];
    const float w20 = Ws[8],  w21 = Ws[9],  w22 = Ws[10], w23 = Ws[11];
    const float w30 = Ws[12], w31 = Ws[13], w32 = Ws[14], w33 = Ws[15];
    const float b0 = Ws[16], b1 = Ws[17], b2 = Ws[18], b3 = Ws[19];

    float4* __restrict__ o0 = (float4*)(out + base);
    float4* __restrict__ o1 = o0 + SP4;
    float4* __restrict__ o2 = o0 + 2 * SP4;
    float4* __restrict__ o3 = o0 + 3 * SP4;

    // First iteration with pre-loaded data.
    {
        float4 r0, r1, r2, r3;
        r0.x = fmaf(w00, a0.x, fmaf(w01, e0.x, fmaf(w02, f0.x, fmaf(w03, h0.x, -b0))));
        r0.y = fmaf(w00, a0.y, fmaf(w01, e0.y, fmaf(w02, f0.y, fmaf(w03, h0.y, -b0))));
        r0.z = fmaf(w00, a0.z, fmaf(w01, e0.z, fmaf(w02, f0.z, fmaf(w03, h0.z, -b0))));
        r0.w = fmaf(w00, a0.w, fmaf(w01, e0.w, fmaf(w02, f0.w, fmaf(w03, h0.w, -b0))));
        r1.x = fmaf(w10, a0.x, fmaf(w11, e0.x, fmaf(w12, f0.x, fmaf(w13, h0.x, -b1))));
        r1.y = fmaf(w10, a0.y, fmaf(w11, e0.y, fmaf(w12, f0.y, fmaf(w13, h0.y, -b1))));
        r1.z = fmaf(w10, a0.z, fmaf(w11, e0.z, fmaf(w12, f0.z, fmaf(w13, h0.z, -b1))));
        r1.w = fmaf(w10, a0.w, fmaf(w11, e0.w, fmaf(w12, f0.w, fmaf(w13, h0.w, -b1))));
        r2.x = fmaf(w20, a0.x, fmaf(w21, e0.x, fmaf(w22, f0.x, fmaf(w23, h0.x, -b2))));
        r2.y = fmaf(w20, a0.y, fmaf(w21, e0.y, fmaf(w22, f0.y, fmaf(w23, h0.y, -b2))));
        r2.z = fmaf(w20, a0.z, fmaf(w21, e0.z, fmaf(w22, f0.z, fmaf(w23, h0.z, -b2))));
        r2.w = fmaf(w20, a0.w, fmaf(w21, e0.w, fmaf(w22, f0.w, fmaf(w23, h0.w, -b2))));
        r3.x = fmaf(w30, a0.x, fmaf(w31, e0.x, fmaf(w32, f0.x, fmaf(w33, h0.x, -b3))));
        r3.y = fmaf(w30, a0.y, fmaf(w31, e0.y, fmaf(w32, f0.y, fmaf(w33, h0.y, -b3))));
        r3.z = fmaf(w30, a0.z, fmaf(w31, e0.z, fmaf(w32, f0.z, fmaf(w33, h0.z, -b3))));
        r3.w = fmaf(w30, a0.w, fmaf(w31, e0.w, fmaf(w32, f0.w, fmaf(w33, h0.w, -b3))));
        __stcs(o0 + tid, r0);
        __stcs(o1 + tid, r1);
        __stcs(o2 + tid, r2);
        __stcs(o3 + tid, r3);
    }

    for (int i = tid + 256; i < SP4; i += 256) {
        float4 a = __ldcs(c0 + i);
        float4 e = __ldcs(c1 + i);
        float4 f = __ldcs(c2 + i);
        float4 h = __ldcs(c3 + i);

        float4 r0, r1, r2, r3;
        r0.x = fmaf(w00, a.x, fmaf(w01, e.x, fmaf(w02, f.x, fmaf(w03, h.x, -b0))));
        r0.y = fmaf(w00, a.y, fmaf(w01, e.y, fmaf(w02, f.y, fmaf(w03, h.y, -b0))));
        r0.z = fmaf(w00, a.z, fmaf(w01, e.z, fmaf(w02, f.z, fmaf(w03, h.z, -b0))));
        r0.w = fmaf(w00, a.w, fmaf(w01, e.w, fmaf(w02, f.w, fmaf(w03, h.w, -b0))));
        r1.x = fmaf(w10, a.x, fmaf(w11, e.x, fmaf(w12, f.x, fmaf(w13, h.x, -b1))));
        r1.y = fmaf(w10, a.y, fmaf(w11, e.y, fmaf(w12, f.y, fmaf(w13, h.y, -b1))));
        r1.z = fmaf(w10, a.z, fmaf(w11, e.z, fmaf(w12, f.z, fmaf(w13, h.z, -b1))));
        r1.w = fmaf(w10, a.w, fmaf(w11, e.w, fmaf(w12, f.w, fmaf(w13, h.w, -b1))));
        r2.x = fmaf(w20, a.x, fmaf(w21, e.x, fmaf(w22, f.x, fmaf(w23, h.x, -b2))));
        r2.y = fmaf(w20, a.y, fmaf(w21, e.y, fmaf(w22, f.y, fmaf(w23, h.y, -b2))));
        r2.z = fmaf(w20, a.z, fmaf(w21, e.z, fmaf(w22, f.z, fmaf(w23, h.z, -b2))));
        r2.w = fmaf(w20, a.w, fmaf(w21, e.w, fmaf(w22, f.w, fmaf(w23, h.w, -b2))));
        r3.x = fmaf(w30, a.x, fmaf(w31, e.x, fmaf(w32, f.x, fmaf(w33, h.x, -b3))));
        r3.y = fmaf(w30, a.y, fmaf(w31, e.y, fmaf(w32, f.y, fmaf(w33, h.y, -b3))));
        r3.z = fmaf(w30, a.z, fmaf(w31, e.z, fmaf(w32, f.z, fmaf(w33, h.z, -b3))));
        r3.w = fmaf(w30, a.w, fmaf(w31, e.w, fmaf(w32, f.w, fmaf(w33, h.w, -b3))));

        __stcs(o0 + i, r0);
        __stcs(o1 + i, r1);
        __stcs(o2 + i, r2);
        __stcs(o3 + i, r3);
    }
}

// ---------------------------------------------------------------------------
extern "C" void kernel_launch(void* const* d_in, const int* in_sizes, int n_in,
                              void* d_out, int out_size) {
    const float* x = (const float*)d_in[0];
    float* out = (float*)d_out;

    stats_kernel<<<dim3(NB, NG), 256>>>(x);

    cudaLaunchConfig_t cfg = {};
    cfg.gridDim = dim3(NG, NB);
    cfg.blockDim = dim3(256);
    cfg.dynamicSmemBytes = 0;
    cfg.stream = 0;
    cudaLaunchAttribute attrs[1];
    attrs[0].id = cudaLaunchAttributeProgrammaticStreamSerialization;
    attrs[0].val.programmaticStreamSerializationAllowed = 1;
    cfg.attrs = attrs;
    cfg.numAttrs = 1;
    cudaLaunchKernelEx(&cfg, apply_kernel, x, out);
}